// round 1
// baseline (speedup 1.0000x reference)
#include <cuda_runtime.h>
#include <math.h>

// Problem constants
#define BATCH 64
#define LDIM  1024
#define FFDIM 8192      // (H+W)*R*4
#define HDIM  256
#define WDIM  256
#define RDIM  4
#define EPSC  1e-4f

// Scratch (no device allocations allowed)
__device__ float g_mod[BATCH * FFDIM];     // 2 MB
__device__ float g_scale[BATCH * 4];       // per (b,k) normalization scale
__device__ float g_weff[RDIM];
__device__ float g_beff;
__device__ float g_magpart[BATCH * 16];    // per-(b, i-chunk) partial mag sums

// ---------------------------------------------------------------------------
// Kernel 1: fused GEMM  mod[b][f] = (x@Wt^T)[b][f] * silu((x@Wg^T)[b][f])
// BM=64 (all batches), BN=32 cols, BK=16. 128 threads; each thread: 8 rows x 2
// cols x 2 gemms = 32 accumulators.
// ---------------------------------------------------------------------------
#define GBN 32
#define GBK 16

__global__ void __launch_bounds__(128, 2)
k_gemm_silu(const float* __restrict__ x,
            const float* __restrict__ Wt,
            const float* __restrict__ Wg)
{
    __shared__ float xs[GBK][BATCH];   // [k][b]  4 KB
    __shared__ float wts[GBK][GBN];    // 2 KB
    __shared__ float wgs[GBK][GBN];    // 2 KB

    const int f0 = blockIdx.x * GBN;
    const int t  = threadIdx.x;
    const int tx = t & 15;     // column pair selector (0..15)
    const int ty = t >> 4;     // row group (0..7), 8 rows each

    float at[8][2], ag[8][2];
#pragma unroll
    for (int r = 0; r < 8; r++) {
        at[r][0] = at[r][1] = 0.f;
        ag[r][0] = ag[r][1] = 0.f;
    }

    for (int k0 = 0; k0 < LDIM; k0 += GBK) {
        // load x tile: 64x16 = 1024 floats, 8 per thread
#pragma unroll
        for (int i = 0; i < 8; i++) {
            int idx = t + i * 128;          // 0..1023
            int l = idx & 15, b = idx >> 4;
            xs[l][b] = x[b * LDIM + k0 + l];
        }
        // load W tiles: 32x16 = 512 floats each, 4 per thread
#pragma unroll
        for (int i = 0; i < 4; i++) {
            int idx = t + i * 128;          // 0..511
            int l = idx & 15, f = idx >> 4;
            const int off = (f0 + f) * LDIM + k0 + l;
            wts[l][f] = Wt[off];
            wgs[l][f] = Wg[off];
        }
        __syncthreads();

#pragma unroll
        for (int kk = 0; kk < GBK; kk++) {
            float xr[8];
#pragma unroll
            for (int r = 0; r < 8; r++) xr[r] = xs[kk][ty * 8 + r];
            float wt0 = wts[kk][tx * 2], wt1 = wts[kk][tx * 2 + 1];
            float wg0 = wgs[kk][tx * 2], wg1 = wgs[kk][tx * 2 + 1];
#pragma unroll
            for (int r = 0; r < 8; r++) {
                at[r][0] = fmaf(xr[r], wt0, at[r][0]);
                at[r][1] = fmaf(xr[r], wt1, at[r][1]);
                ag[r][0] = fmaf(xr[r], wg0, ag[r][0]);
                ag[r][1] = fmaf(xr[r], wg1, ag[r][1]);
            }
        }
        __syncthreads();
    }

#pragma unroll
    for (int r = 0; r < 8; r++) {
#pragma unroll
        for (int c = 0; c < 2; c++) {
            int b = ty * 8 + r;
            int f = f0 + tx * 2 + c;
            float g = ag[r][c];
            float sig = 1.0f / (1.0f + expf(-g));
            g_mod[b * FFDIM + f] = at[r][c] * (g * sig);
        }
    }
}

// ---------------------------------------------------------------------------
// Block reduction helper (256 threads)
// ---------------------------------------------------------------------------
__device__ __forceinline__ float block_reduce_256(float v, float* sh)
{
#pragma unroll
    for (int o = 16; o > 0; o >>= 1) v += __shfl_xor_sync(0xFFFFFFFFu, v, o);
    int w = threadIdx.x >> 5;
    if ((threadIdx.x & 31) == 0) sh[w] = v;
    __syncthreads();
    if (threadIdx.x < 8) {
        v = sh[threadIdx.x];
#pragma unroll
        for (int o = 4; o > 0; o >>= 1) v += __shfl_xor_sync(0x000000FFu, v, o);
    }
    return v;   // valid in thread 0
}

// ---------------------------------------------------------------------------
// Kernel 2: per-(b,k) normalization scales + conv reductions
// grid = 256 blocks (one per (b,k) group of 2048), 256 threads
// ---------------------------------------------------------------------------
__global__ void k_scale(const float* __restrict__ conv_w,
                        const float* __restrict__ conv_b)
{
    __shared__ float sh[8];
    const int g = blockIdx.x;                 // g = b*4 + k
    const float* p = g_mod + g * 2048;
    float s = 0.f;
    for (int i = threadIdx.x; i < 2048; i += 256) s += fabsf(p[i]);
    s = block_reduce_256(s, sh);
    if (threadIdx.x == 0)
        g_scale[g] = rsqrtf(s * (1.0f / 2048.0f) + EPSC);

    if (g == 0) {
        if (threadIdx.x < RDIM) {
            float w = 0.f;
#pragma unroll
            for (int i = 0; i < RDIM; i++) w += conv_w[i * RDIM + threadIdx.x];
            g_weff[threadIdx.x] = w;
        }
        if (threadIdx.x == RDIM) {
            float b = 0.f;
#pragma unroll
            for (int i = 0; i < RDIM; i++) b += conv_b[i];
            g_beff = b;
        }
    }
}

// ---------------------------------------------------------------------------
// Kernel 3: per-batch magnitude partial sums.
// grid = (16 i-chunks, 64 batches), 256 threads. Each block: 16 rows x 256 cols.
// ---------------------------------------------------------------------------
__global__ void k_mag(const float* __restrict__ ws,   // weights_static (2,H,W,2)
                      const float* __restrict__ wm)   // weights_mod (4,H,W)
{
    __shared__ float sa[2][RDIM][16];     // a_part slice, scaled
    __shared__ float sbp[2][RDIM][WDIM];  // b_part, scaled
    __shared__ float sh[8];

    const int b  = blockIdx.y;
    const int i0 = blockIdx.x * 16;
    const int t  = threadIdx.x;

    if (t < 128) {
        int k = t >> 6, r = (t >> 4) & 3, il = t & 15;
        sa[k][r][il] = g_mod[b * FFDIM + k * 2048 + r * 512 + (i0 + il)]
                       * g_scale[b * 4 + k];
    }
#pragma unroll
    for (int it = 0; it < 8; it++) {
        int idx = t + it * 256;           // 0..2047
        int k = idx >> 10, r = (idx >> 8) & 3, j = idx & 255;
        sbp[k][r][j] = g_mod[b * FFDIM + k * 2048 + r * 512 + HDIM + j]
                       * g_scale[b * 4 + k];
    }
    __syncthreads();

    const float w0 = g_weff[0], w1 = g_weff[1], w2 = g_weff[2], w3 = g_weff[3];
    const float be = g_beff;

    float sum = 0.f;
#pragma unroll
    for (int it = 0; it < 16; it++) {
        const int il = it;
        const int j  = t;
        const int i  = i0 + il;
        const int pix = (i << 8) + j;
        float m[2];
#pragma unroll
        for (int k = 0; k < 2; k++) {
            float acc = be;
            acc = fmaf(w0 * sa[k][0][il], sbp[k][0][j], acc);
            acc = fmaf(w1 * sa[k][1][il], sbp[k][1][j], acc);
            acc = fmaf(w2 * sa[k][2][il], sbp[k][2][j], acc);
            acc = fmaf(w3 * sa[k][3][il], sbp[k][3][j], acc);
            m[k] = wm[(k << 16) + pix] * acc;
        }
        float A1re = ws[131072 + 2 * pix];
        float A1im = ws[131072 + 2 * pix + 1];
        float re = A1re * m[0] - A1im * m[1];
        float im = A1re * m[1] - A1im * m[0];
        sum += sqrtf(re * re + im * im + EPSC);
    }
    sum = block_reduce_256(sum, sh);
    if (t == 0) g_magpart[b * 16 + blockIdx.x] = sum;
}

// ---------------------------------------------------------------------------
// Kernel 4: final output. grid = (16 i-chunks, 64 batches), 256 threads.
// ---------------------------------------------------------------------------
__global__ void k_final(const float* __restrict__ ws,
                        const float* __restrict__ wm,
                        float* __restrict__ out)
{
    __shared__ float sa[4][RDIM][16];
    __shared__ float sbp[4][RDIM][WDIM];   // 16 KB

    const int b  = blockIdx.y;
    const int i0 = blockIdx.x * 16;
    const int t  = threadIdx.x;

    if (t < 256) {
        int k = t >> 6, r = (t >> 4) & 3, il = t & 15;
        sa[k][r][il] = g_mod[b * FFDIM + k * 2048 + r * 512 + (i0 + il)]
                       * g_scale[b * 4 + k];
    }
#pragma unroll
    for (int it = 0; it < 16; it++) {
        int idx = t + it * 256;            // 0..4095
        int k = idx >> 10, r = (idx >> 8) & 3, j = idx & 255;
        sbp[k][r][j] = g_mod[b * FFDIM + k * 2048 + r * 512 + HDIM + j]
                       * g_scale[b * 4 + k];
    }
    __syncthreads();

    // deterministic reduction of per-batch mag partials
    float msum = 0.f;
#pragma unroll
    for (int q = 0; q < 16; q++) msum += g_magpart[b * 16 + q];
    const float inv = rsqrtf(msum * (1.0f / 65536.0f) + EPSC);

    const float w0 = g_weff[0], w1 = g_weff[1], w2 = g_weff[2], w3 = g_weff[3];
    const float be = g_beff;

#pragma unroll
    for (int it = 0; it < 16; it++) {
        const int il = it;
        const int j  = t;
        const int i  = i0 + il;
        const int pix = (i << 8) + j;
        float m[4];
#pragma unroll
        for (int k = 0; k < 4; k++) {
            float acc = be;
            acc = fmaf(w0 * sa[k][0][il], sbp[k][0][j], acc);
            acc = fmaf(w1 * sa[k][1][il], sbp[k][1][j], acc);
            acc = fmaf(w2 * sa[k][2][il], sbp[k][2][j], acc);
            acc = fmaf(w3 * sa[k][3][il], sbp[k][3][j], acc);
            m[k] = wm[(k << 16) + pix] * acc;
        }
        float A0re = ws[2 * pix];
        float A0im = ws[2 * pix + 1];
        float A1re = ws[131072 + 2 * pix];
        float A1im = ws[131072 + 2 * pix + 1];
        float re = A1re * m[0] - A1im * m[1];
        float im = A1re * m[1] - A1im * m[0];
        float mwre = fmaf(re, inv, A0re);
        float mwim = fmaf(im, inv, A0im);
        float den = sqrtf(fmaf(m[2], m[2], fmaf(m[3], m[3], EPSC)));
        out[(b << 16) + pix] = (mwre * m[2] + mwim * m[3]) / den;
    }
}

// ---------------------------------------------------------------------------
// Launch
// ---------------------------------------------------------------------------
extern "C" void kernel_launch(void* const* d_in, const int* in_sizes, int n_in,
                              void* d_out, int out_size)
{
    const float* x      = (const float*)d_in[0];   // (64, 1024)
    const float* Wt     = (const float*)d_in[1];   // (8192, 1024)
    const float* Wg     = (const float*)d_in[2];   // (8192, 1024)
    const float* ws     = (const float*)d_in[3];   // (2, 256, 256, 2)
    const float* wm     = (const float*)d_in[4];   // (4, 256, 256)
    const float* conv_w = (const float*)d_in[5];   // (4, 4)
    const float* conv_b = (const float*)d_in[6];   // (4,)
    float* out = (float*)d_out;                    // (64, 256, 256)

    k_gemm_silu<<<FFDIM / GBN, 128>>>(x, Wt, Wg);
    k_scale<<<BATCH * 4, 256>>>(conv_w, conv_b);
    k_mag<<<dim3(16, BATCH), 256>>>(ws, wm);
    k_final<<<dim3(16, BATCH), 256>>>(ws, wm, out);
}

// round 2
// speedup vs baseline: 1.1930x; 1.1930x over previous
#include <cuda_runtime.h>
#include <math.h>

// Problem constants
#define BATCH 64
#define LDIM  1024
#define FFDIM 8192      // (H+W)*R*4
#define HDIM  256
#define WDIM  256
#define RDIM  4
#define EPSC  1e-4f

// Scratch (no device allocations allowed)
__device__ float g_mod[BATCH * FFDIM];     // 2 MB
__device__ float g_scale[BATCH * 4];
__device__ float g_weff[RDIM];
__device__ float g_beff;
__device__ float g_magpart[BATCH * 16];

// ---------------------------------------------------------------------------
// packed f32x2 helpers
// ---------------------------------------------------------------------------
__device__ __forceinline__ unsigned long long fma2(unsigned long long a,
                                                   unsigned long long b,
                                                   unsigned long long c)
{
    unsigned long long d;
    asm("fma.rn.f32x2 %0, %1, %2, %3;" : "=l"(d) : "l"(a), "l"(b), "l"(c));
    return d;
}

__device__ __forceinline__ float2 u2f(unsigned long long v)
{
    float2 f;
    f.x = __uint_as_float((unsigned)(v & 0xFFFFFFFFull));
    f.y = __uint_as_float((unsigned)(v >> 32));
    return f;
}

// ---------------------------------------------------------------------------
// Kernel 1: fused GEMM  mod[b][f] = (x@Wt^T)[b][f] * silu((x@Wg^T)[b][f])
// M=64 (batch, packed 2-per-f32x2), N=32 cols, K-tile=16. 128 threads.
// Per thread: 4 row-pairs x 2 cols x 2 gemms = 16 f32x2 accumulators.
// ---------------------------------------------------------------------------
#define GBN 32
#define GBK 16

__global__ void __launch_bounds__(128, 2)
k_gemm_silu(const float* __restrict__ x,
            const float* __restrict__ Wt,
            const float* __restrict__ Wg)
{
    __shared__ __align__(16) float  xs[GBK][BATCH];    // 4 KB, [k][b]
    __shared__ __align__(16) float2 wts2[GBK][GBN];    // 4 KB, duplicated (w,w)
    __shared__ __align__(16) float2 wgs2[GBK][GBN];    // 4 KB

    const int f0 = blockIdx.x * GBN;
    const int t  = threadIdx.x;
    const int tx = t & 15;     // col pair (2 cols)
    const int ty = t >> 4;     // 8 consecutive batch rows

    unsigned long long at2[4][2], ag2[4][2];
#pragma unroll
    for (int r = 0; r < 4; r++)
        at2[r][0] = at2[r][1] = ag2[r][0] = ag2[r][1] = 0ull;

    // prefetch registers
    float  xp[8];
    float4 wtp, wgp;
    const int wf  = t >> 2;          // 0..31
    const int wl4 = (t & 3) * 4;     // 0,4,8,12

    // ---- prefetch tile 0 ----
    {
        const int k0 = 0;
#pragma unroll
        for (int i = 0; i < 8; i++) {
            int idx = t + i * 128;
            xp[i] = x[(idx >> 4) * LDIM + k0 + (idx & 15)];
        }
        wtp = *reinterpret_cast<const float4*>(&Wt[(size_t)(f0 + wf) * LDIM + k0 + wl4]);
        wgp = *reinterpret_cast<const float4*>(&Wg[(size_t)(f0 + wf) * LDIM + k0 + wl4]);
    }

    for (int kt = 0; kt < LDIM / GBK; ++kt) {
        // store prefetched tile to smem
#pragma unroll
        for (int i = 0; i < 8; i++) {
            int idx = t + i * 128;
            xs[idx & 15][idx >> 4] = xp[i];
        }
        wts2[wl4 + 0][wf] = make_float2(wtp.x, wtp.x);
        wts2[wl4 + 1][wf] = make_float2(wtp.y, wtp.y);
        wts2[wl4 + 2][wf] = make_float2(wtp.z, wtp.z);
        wts2[wl4 + 3][wf] = make_float2(wtp.w, wtp.w);
        wgs2[wl4 + 0][wf] = make_float2(wgp.x, wgp.x);
        wgs2[wl4 + 1][wf] = make_float2(wgp.y, wgp.y);
        wgs2[wl4 + 2][wf] = make_float2(wgp.z, wgp.z);
        wgs2[wl4 + 3][wf] = make_float2(wgp.w, wgp.w);
        __syncthreads();

        // prefetch next tile (LDGs fly during compute)
        if (kt + 1 < LDIM / GBK) {
            const int k0 = (kt + 1) * GBK;
#pragma unroll
            for (int i = 0; i < 8; i++) {
                int idx = t + i * 128;
                xp[i] = x[(idx >> 4) * LDIM + k0 + (idx & 15)];
            }
            wtp = *reinterpret_cast<const float4*>(&Wt[(size_t)(f0 + wf) * LDIM + k0 + wl4]);
            wgp = *reinterpret_cast<const float4*>(&Wg[(size_t)(f0 + wf) * LDIM + k0 + wl4]);
        }

#pragma unroll
        for (int kk = 0; kk < GBK; kk++) {
            ulonglong2 xv0 = *reinterpret_cast<const ulonglong2*>(&xs[kk][ty * 8]);
            ulonglong2 xv1 = *reinterpret_cast<const ulonglong2*>(&xs[kk][ty * 8 + 4]);
            ulonglong2 wt  = *reinterpret_cast<const ulonglong2*>(&wts2[kk][tx * 2]);
            ulonglong2 wg  = *reinterpret_cast<const ulonglong2*>(&wgs2[kk][tx * 2]);

            at2[0][0] = fma2(xv0.x, wt.x, at2[0][0]);
            at2[0][1] = fma2(xv0.x, wt.y, at2[0][1]);
            at2[1][0] = fma2(xv0.y, wt.x, at2[1][0]);
            at2[1][1] = fma2(xv0.y, wt.y, at2[1][1]);
            at2[2][0] = fma2(xv1.x, wt.x, at2[2][0]);
            at2[2][1] = fma2(xv1.x, wt.y, at2[2][1]);
            at2[3][0] = fma2(xv1.y, wt.x, at2[3][0]);
            at2[3][1] = fma2(xv1.y, wt.y, at2[3][1]);

            ag2[0][0] = fma2(xv0.x, wg.x, ag2[0][0]);
            ag2[0][1] = fma2(xv0.x, wg.y, ag2[0][1]);
            ag2[1][0] = fma2(xv0.y, wg.x, ag2[1][0]);
            ag2[1][1] = fma2(xv0.y, wg.y, ag2[1][1]);
            ag2[2][0] = fma2(xv1.x, wg.x, ag2[2][0]);
            ag2[2][1] = fma2(xv1.x, wg.y, ag2[2][1]);
            ag2[3][0] = fma2(xv1.y, wg.x, ag2[3][0]);
            ag2[3][1] = fma2(xv1.y, wg.y, ag2[3][1]);
        }
        __syncthreads();
    }

    // epilogue: silu-gate and store
    const int fcol = f0 + tx * 2;
#pragma unroll
    for (int r = 0; r < 4; r++) {
        float2 t0 = u2f(at2[r][0]);   // col 0, rows (b, b+1)
        float2 t1 = u2f(at2[r][1]);   // col 1
        float2 g0 = u2f(ag2[r][0]);
        float2 g1 = u2f(ag2[r][1]);
        int b = ty * 8 + 2 * r;

        float2 o0, o1;
        o0.x = t0.x * __fdividef(g0.x, 1.0f + __expf(-g0.x));
        o0.y = t1.x * __fdividef(g1.x, 1.0f + __expf(-g1.x));
        o1.x = t0.y * __fdividef(g0.y, 1.0f + __expf(-g0.y));
        o1.y = t1.y * __fdividef(g1.y, 1.0f + __expf(-g1.y));

        *reinterpret_cast<float2*>(&g_mod[(size_t)b * FFDIM + fcol])       = o0;
        *reinterpret_cast<float2*>(&g_mod[(size_t)(b + 1) * FFDIM + fcol]) = o1;
    }
}

// ---------------------------------------------------------------------------
// Block reduction helper (256 threads)
// ---------------------------------------------------------------------------
__device__ __forceinline__ float block_reduce_256(float v, float* sh)
{
#pragma unroll
    for (int o = 16; o > 0; o >>= 1) v += __shfl_xor_sync(0xFFFFFFFFu, v, o);
    int w = threadIdx.x >> 5;
    if ((threadIdx.x & 31) == 0) sh[w] = v;
    __syncthreads();
    if (threadIdx.x < 8) {
        v = sh[threadIdx.x];
#pragma unroll
        for (int o = 4; o > 0; o >>= 1) v += __shfl_xor_sync(0x000000FFu, v, o);
    }
    return v;   // valid in thread 0
}

// ---------------------------------------------------------------------------
// Kernel 2: per-(b,k) normalization scales + conv reductions
// ---------------------------------------------------------------------------
__global__ void k_scale(const float* __restrict__ conv_w,
                        const float* __restrict__ conv_b)
{
    __shared__ float sh[8];
    const int g = blockIdx.x;                 // g = b*4 + k
    const float* p = g_mod + (size_t)g * 2048;
    float s = 0.f;
    for (int i = threadIdx.x; i < 2048; i += 256) s += fabsf(p[i]);
    s = block_reduce_256(s, sh);
    if (threadIdx.x == 0)
        g_scale[g] = rsqrtf(s * (1.0f / 2048.0f) + EPSC);

    if (g == 0) {
        if (threadIdx.x < RDIM) {
            float w = 0.f;
#pragma unroll
            for (int i = 0; i < RDIM; i++) w += conv_w[i * RDIM + threadIdx.x];
            g_weff[threadIdx.x] = w;
        }
        if (threadIdx.x == RDIM) {
            float b = 0.f;
#pragma unroll
            for (int i = 0; i < RDIM; i++) b += conv_b[i];
            g_beff = b;
        }
    }
}

// ---------------------------------------------------------------------------
// Kernel 3: per-batch magnitude partial sums.
// grid = (16 i-chunks, 64 batches), 256 threads (thread = column j).
// ---------------------------------------------------------------------------
__global__ void __launch_bounds__(256)
k_mag(const float* __restrict__ ws,   // weights_static (2,H,W,2)
      const float* __restrict__ wm)   // weights_mod (4,H,W)
{
    __shared__ float wa[2][RDIM][16];   // w_r * a * scale
    __shared__ float sh[8];

    const int b  = blockIdx.y;
    const int i0 = blockIdx.x * 16;
    const int t  = threadIdx.x;

    if (t < 128) {
        int k = t >> 6, r = (t >> 4) & 3, il = t & 15;
        wa[k][r][il] = g_weff[r] * g_scale[b * 4 + k]
                     * g_mod[(size_t)b * FFDIM + k * 2048 + r * 512 + (i0 + il)];
    }

    float sb[2][RDIM];
#pragma unroll
    for (int k = 0; k < 2; k++) {
        float sc = g_scale[b * 4 + k];
#pragma unroll
        for (int r = 0; r < RDIM; r++)
            sb[k][r] = sc * g_mod[(size_t)b * FFDIM + k * 2048 + r * 512 + HDIM + t];
    }
    __syncthreads();

    const float be = g_beff;
    float sum = 0.f;
#pragma unroll
    for (int il = 0; il < 16; il++) {
        const int pix = ((i0 + il) << 8) + t;
        float m0 = be, m1 = be;
#pragma unroll
        for (int r = 0; r < RDIM; r++) {
            m0 = fmaf(wa[0][r][il], sb[0][r], m0);
            m1 = fmaf(wa[1][r][il], sb[1][r], m1);
        }
        m0 *= wm[pix];
        m1 *= wm[65536 + pix];
        float2 A1 = *reinterpret_cast<const float2*>(&ws[131072 + 2 * pix]);
        float re = A1.x * m0 - A1.y * m1;
        float im = A1.x * m1 - A1.y * m0;
        sum += sqrtf(fmaf(re, re, fmaf(im, im, EPSC)));
    }
    sum = block_reduce_256(sum, sh);
    if (t == 0) g_magpart[b * 16 + blockIdx.x] = sum;
}

// ---------------------------------------------------------------------------
// Kernel 4: final output. grid = (16 i-chunks, 64 batches), 256 threads.
// ---------------------------------------------------------------------------
__global__ void __launch_bounds__(256)
k_final(const float* __restrict__ ws,
        const float* __restrict__ wm,
        float* __restrict__ out)
{
    __shared__ float wa[4][RDIM][16];

    const int b  = blockIdx.y;
    const int i0 = blockIdx.x * 16;
    const int t  = threadIdx.x;

    {
        int k = t >> 6, r = (t >> 4) & 3, il = t & 15;
        wa[k][r][il] = g_weff[r] * g_scale[b * 4 + k]
                     * g_mod[(size_t)b * FFDIM + k * 2048 + r * 512 + (i0 + il)];
    }

    float sb[4][RDIM];
#pragma unroll
    for (int k = 0; k < 4; k++) {
        float sc = g_scale[b * 4 + k];
#pragma unroll
        for (int r = 0; r < RDIM; r++)
            sb[k][r] = sc * g_mod[(size_t)b * FFDIM + k * 2048 + r * 512 + HDIM + t];
    }
    __syncthreads();

    // deterministic reduction of per-batch mag partials
    float msum = 0.f;
#pragma unroll
    for (int q = 0; q < 16; q++) msum += g_magpart[b * 16 + q];
    const float inv = rsqrtf(msum * (1.0f / 65536.0f) + EPSC);
    const float be = g_beff;

#pragma unroll
    for (int il = 0; il < 16; il++) {
        const int pix = ((i0 + il) << 8) + t;
        float m[4];
#pragma unroll
        for (int k = 0; k < 4; k++) {
            float acc = be;
#pragma unroll
            for (int r = 0; r < RDIM; r++)
                acc = fmaf(wa[k][r][il], sb[k][r], acc);
            m[k] = wm[(k << 16) + pix] * acc;
        }
        float2 A0 = *reinterpret_cast<const float2*>(&ws[2 * pix]);
        float2 A1 = *reinterpret_cast<const float2*>(&ws[131072 + 2 * pix]);
        float re = A1.x * m[0] - A1.y * m[1];
        float im = A1.x * m[1] - A1.y * m[0];
        float mwre = fmaf(re, inv, A0.x);
        float mwim = fmaf(im, inv, A0.y);
        float den = sqrtf(fmaf(m[2], m[2], fmaf(m[3], m[3], EPSC)));
        out[((size_t)b << 16) + pix] =
            __fdividef(fmaf(mwre, m[2], mwim * m[3]), den);
    }
}

// ---------------------------------------------------------------------------
// Launch
// ---------------------------------------------------------------------------
extern "C" void kernel_launch(void* const* d_in, const int* in_sizes, int n_in,
                              void* d_out, int out_size)
{
    const float* x      = (const float*)d_in[0];   // (64, 1024)
    const float* Wt     = (const float*)d_in[1];   // (8192, 1024)
    const float* Wg     = (const float*)d_in[2];   // (8192, 1024)
    const float* ws     = (const float*)d_in[3];   // (2, 256, 256, 2)
    const float* wm     = (const float*)d_in[4];   // (4, 256, 256)
    const float* conv_w = (const float*)d_in[5];   // (4, 4)
    const float* conv_b = (const float*)d_in[6];   // (4,)
    float* out = (float*)d_out;                    // (64, 256, 256)

    k_gemm_silu<<<FFDIM / GBN, 128>>>(x, Wt, Wg);
    k_scale<<<BATCH * 4, 256>>>(conv_w, conv_b);
    k_mag<<<dim3(16, BATCH), 256>>>(ws, wm);
    k_final<<<dim3(16, BATCH), 256>>>(ws, wm, out);
}

// round 4
// speedup vs baseline: 2.3903x; 2.0036x over previous
#include <cuda_runtime.h>
#include <math.h>
#include <stdint.h>

// Problem constants
#define BATCH 64
#define LDIM  1024
#define FFDIM 8192
#define HDIM  256
#define RDIM  4
#define EPSC  1e-4f

// Scratch
__device__ float g_mod[BATCH * FFDIM];     // 2 MB, layout [b][f]
__device__ float g_scale[BATCH * 4];
__device__ float g_weff[RDIM];
__device__ float g_beff;
__device__ float g_magpart[BATCH * 16];

// ---------------------------------------------------------------------------
// tf32 helpers (family-portable: mma.sync sm_80+, no 'a'-suffix features)
// ---------------------------------------------------------------------------
__device__ __forceinline__ void tf32_split(float v, uint32_t& hi, uint32_t& lo)
{
    uint32_t h;
    asm("cvt.rna.tf32.f32 %0, %1;" : "=r"(h) : "f"(v));
    float r = v - __uint_as_float(h);
    asm("cvt.rna.tf32.f32 %0, %1;" : "=r"(lo) : "f"(r));
    hi = h;
}

__device__ __forceinline__ void mma8(float* d, const uint32_t* a, const uint32_t* b)
{
    asm volatile(
        "mma.sync.aligned.m16n8k8.row.col.f32.tf32.tf32.f32 "
        "{%0,%1,%2,%3}, {%4,%5,%6,%7}, {%8,%9}, {%0,%1,%2,%3};"
        : "+f"(d[0]), "+f"(d[1]), "+f"(d[2]), "+f"(d[3])
        : "r"(a[0]), "r"(a[1]), "r"(a[2]), "r"(a[3]), "r"(b[0]), "r"(b[1]));
}

// ---------------------------------------------------------------------------
// Kernel 1: fused GEMM pair + silu via mma.sync tf32 (3xTF32 split).
// CTA tile: M=64 f-rows x N=64 batch, K=1024 in 32-wide tiles, double buffer.
// 4 warps: warp tile M=32 x N=32, two gemms (Wt, Wg) sharing B=x fragments.
// ---------------------------------------------------------------------------
#define TSTR   36                  // padded row stride (floats), conflict-free
#define TILE_F (64 * TSTR)         // one 64x32 tile (padded)
#define STAGE_F (3 * TILE_F)       // Wt + Wg + x
#define GEMM_SMEM_BYTES (2 * STAGE_F * 4)   // 55296 B

__global__ void __launch_bounds__(128, 1)
k_gemm_mma(const float* __restrict__ x,
           const float* __restrict__ Wt,
           const float* __restrict__ Wg)
{
    extern __shared__ float smem[];
    const int t    = threadIdx.x;
    const int warp = t >> 5, lane = t & 31;
    const int gid  = lane >> 2, tig = lane & 3;
    const int mb   = (warp & 1) * 32;     // warp M offset (f)
    const int nb   = (warp >> 1) * 32;    // warp N offset (batch)
    const int f0   = blockIdx.x * 64;

    const float4* Wt4 = reinterpret_cast<const float4*>(Wt);
    const float4* Wg4 = reinterpret_cast<const float4*>(Wg);
    const float4* X4  = reinterpret_cast<const float4*>(x);

    float acc[2][2][4][4];
#pragma unroll
    for (int g = 0; g < 2; g++)
#pragma unroll
        for (int i = 0; i < 2; i++)
#pragma unroll
            for (int j = 0; j < 4; j++)
#pragma unroll
                for (int c = 0; c < 4; c++) acc[g][i][j][c] = 0.f;

    float4 wtp[4], wgp[4], xp[4];
    // prefetch k-tile 0
#pragma unroll
    for (int q = 0; q < 4; q++) {
        int idx = q * 128 + t, row = idx >> 3, col = idx & 7;
        wtp[q] = Wt4[(size_t)(f0 + row) * 256 + col];
        wgp[q] = Wg4[(size_t)(f0 + row) * 256 + col];
        xp[q]  = X4[(size_t)row * 256 + col];
    }

    for (int kt = 0; kt < 32; ++kt) {
        float* st = smem + (kt & 1) * STAGE_F;
#pragma unroll
        for (int q = 0; q < 4; q++) {
            int idx = q * 128 + t, row = idx >> 3, col = idx & 7;
            *reinterpret_cast<float4*>(st + row * TSTR + col * 4)              = wtp[q];
            *reinterpret_cast<float4*>(st + TILE_F + row * TSTR + col * 4)     = wgp[q];
            *reinterpret_cast<float4*>(st + 2 * TILE_F + row * TSTR + col * 4) = xp[q];
        }
        __syncthreads();

        if (kt + 1 < 32) {
            const size_t ko = (size_t)(kt + 1) * 8;
#pragma unroll
            for (int q = 0; q < 4; q++) {
                int idx = q * 128 + t, row = idx >> 3, col = idx & 7;
                wtp[q] = Wt4[(size_t)(f0 + row) * 256 + ko + col];
                wgp[q] = Wg4[(size_t)(f0 + row) * 256 + ko + col];
                xp[q]  = X4[(size_t)row * 256 + ko + col];
            }
        }

#pragma unroll
        for (int ks = 0; ks < 4; ++ks) {
            const int ko = ks * 8;
            uint32_t Ah[2][2][4], Al[2][2][4];
#pragma unroll
            for (int g = 0; g < 2; ++g) {
                const float* Wb = st + g * TILE_F;
#pragma unroll
                for (int i = 0; i < 2; ++i) {
                    int r0 = mb + i * 16 + gid;
                    float v0 = Wb[r0 * TSTR + ko + tig];
                    float v1 = Wb[(r0 + 8) * TSTR + ko + tig];
                    float v2 = Wb[r0 * TSTR + ko + tig + 4];
                    float v3 = Wb[(r0 + 8) * TSTR + ko + tig + 4];
                    tf32_split(v0, Ah[g][i][0], Al[g][i][0]);
                    tf32_split(v1, Ah[g][i][1], Al[g][i][1]);
                    tf32_split(v2, Ah[g][i][2], Al[g][i][2]);
                    tf32_split(v3, Ah[g][i][3], Al[g][i][3]);
                }
            }
            uint32_t Bh[4][2], Bl[4][2];
            const float* Xb = st + 2 * TILE_F;
#pragma unroll
            for (int j = 0; j < 4; ++j) {
                int br = nb + j * 8 + gid;
                float v0 = Xb[br * TSTR + ko + tig];
                float v1 = Xb[br * TSTR + ko + tig + 4];
                tf32_split(v0, Bh[j][0], Bl[j][0]);
                tf32_split(v1, Bh[j][1], Bl[j][1]);
            }
#pragma unroll
            for (int g = 0; g < 2; ++g)
#pragma unroll
                for (int i = 0; i < 2; ++i)
#pragma unroll
                    for (int j = 0; j < 4; ++j) {
                        mma8(acc[g][i][j], Ah[g][i], Bh[j]);
                        mma8(acc[g][i][j], Ah[g][i], Bl[j]);
                        mma8(acc[g][i][j], Al[g][i], Bh[j]);
                    }
        }
    }

    // silu epilogue -> smem transpose -> coalesced float4 stores
    float* sOut = smem;   // 64 (b) x 68-stride (f)
#pragma unroll
    for (int i = 0; i < 2; ++i)
#pragma unroll
        for (int j = 0; j < 4; ++j)
#pragma unroll
            for (int c = 0; c < 4; ++c) {
                float tv = acc[0][i][j][c];
                float gv = acc[1][i][j][c];
                float o  = tv * __fdividef(gv, 1.0f + __expf(-gv));
                int fl = mb + i * 16 + gid + ((c >> 1) << 3);
                int bl = nb + j * 8 + 2 * tig + (c & 1);
                sOut[bl * 68 + fl] = o;
            }
    __syncthreads();

#pragma unroll
    for (int v = 0; v < 8; ++v) {
        int idx = v * 128 + t;
        int row = idx >> 4, q = idx & 15;
        float4 val = *reinterpret_cast<const float4*>(sOut + row * 68 + q * 4);
        *reinterpret_cast<float4*>(&g_mod[(size_t)row * FFDIM + f0 + q * 4]) = val;
    }
}

// ---------------------------------------------------------------------------
// Block reduction helper (256 threads)
// ---------------------------------------------------------------------------
__device__ __forceinline__ float block_reduce_256(float v, float* sh)
{
#pragma unroll
    for (int o = 16; o > 0; o >>= 1) v += __shfl_xor_sync(0xFFFFFFFFu, v, o);
    int w = threadIdx.x >> 5;
    if ((threadIdx.x & 31) == 0) sh[w] = v;
    __syncthreads();
    if (threadIdx.x < 8) {
        v = sh[threadIdx.x];
#pragma unroll
        for (int o = 4; o > 0; o >>= 1) v += __shfl_xor_sync(0x000000FFu, v, o);
    }
    return v;
}

// ---------------------------------------------------------------------------
// Kernel 2: per-(b,k) normalization scales + conv reductions
// ---------------------------------------------------------------------------
__global__ void k_scale(const float* __restrict__ conv_w,
                        const float* __restrict__ conv_b)
{
    __shared__ float sh[8];
    const int g = blockIdx.x;                 // g = b*4 + k
    const float* p = g_mod + (size_t)g * 2048;
    float s = 0.f;
    for (int i = threadIdx.x; i < 2048; i += 256) s += fabsf(p[i]);
    s = block_reduce_256(s, sh);
    if (threadIdx.x == 0)
        g_scale[g] = rsqrtf(s * (1.0f / 2048.0f) + EPSC);

    if (g == 0) {
        if (threadIdx.x < RDIM) {
            float w = 0.f;
#pragma unroll
            for (int i = 0; i < RDIM; i++) w += conv_w[i * RDIM + threadIdx.x];
            g_weff[threadIdx.x] = w;
        }
        if (threadIdx.x == RDIM) {
            float b = 0.f;
#pragma unroll
            for (int i = 0; i < RDIM; i++) b += conv_b[i];
            g_beff = b;
        }
    }
}

// ---------------------------------------------------------------------------
// Kernel 3: per-batch magnitude partial sums.
// ---------------------------------------------------------------------------
__global__ void __launch_bounds__(256)
k_mag(const float* __restrict__ ws, const float* __restrict__ wm)
{
    __shared__ float4 wa4[16][2];    // [il][k] quads over r
    __shared__ float  sh[8];

    const int b  = blockIdx.y;
    const int i0 = blockIdx.x * 16;
    const int t  = threadIdx.x;

    if (t < 128) {
        int k = t >> 6, r = (t >> 4) & 3, il = t & 15;
        reinterpret_cast<float*>(wa4)[il * 8 + k * 4 + r] =
            g_weff[r] * g_scale[b * 4 + k]
            * g_mod[(size_t)b * FFDIM + k * 2048 + r * 512 + (i0 + il)];
    }

    float sb0[4], sb1[4];
    {
        float s0 = g_scale[b * 4 + 0], s1 = g_scale[b * 4 + 1];
#pragma unroll
        for (int r = 0; r < 4; r++) {
            sb0[r] = s0 * g_mod[(size_t)b * FFDIM + 0 * 2048 + r * 512 + HDIM + t];
            sb1[r] = s1 * g_mod[(size_t)b * FFDIM + 1 * 2048 + r * 512 + HDIM + t];
        }
    }
    __syncthreads();

    const float be = g_beff;
    float sum = 0.f;
#pragma unroll
    for (int il = 0; il < 16; il++) {
        const int pix = ((i0 + il) << 8) + t;
        float4 w0 = wa4[il][0];
        float4 w1 = wa4[il][1];
        float m0 = be, m1 = be;
        m0 = fmaf(w0.x, sb0[0], m0); m0 = fmaf(w0.y, sb0[1], m0);
        m0 = fmaf(w0.z, sb0[2], m0); m0 = fmaf(w0.w, sb0[3], m0);
        m1 = fmaf(w1.x, sb1[0], m1); m1 = fmaf(w1.y, sb1[1], m1);
        m1 = fmaf(w1.z, sb1[2], m1); m1 = fmaf(w1.w, sb1[3], m1);
        m0 *= wm[pix];
        m1 *= wm[65536 + pix];
        float2 A1 = *reinterpret_cast<const float2*>(&ws[131072 + 2 * pix]);
        float re = A1.x * m0 - A1.y * m1;
        float im = A1.x * m1 - A1.y * m0;
        sum += sqrtf(fmaf(re, re, fmaf(im, im, EPSC)));
    }
    sum = block_reduce_256(sum, sh);
    if (t == 0) g_magpart[b * 16 + blockIdx.x] = sum;
}

// ---------------------------------------------------------------------------
// Kernel 4: final output.
// ---------------------------------------------------------------------------
__global__ void __launch_bounds__(256)
k_final(const float* __restrict__ ws, const float* __restrict__ wm,
        float* __restrict__ out)
{
    __shared__ float4 wa4[16][4];    // [il][k]

    const int b  = blockIdx.y;
    const int i0 = blockIdx.x * 16;
    const int t  = threadIdx.x;

    {
        int k = t >> 6, r = (t >> 4) & 3, il = t & 15;
        reinterpret_cast<float*>(wa4)[il * 16 + k * 4 + r] =
            g_weff[r] * g_scale[b * 4 + k]
            * g_mod[(size_t)b * FFDIM + k * 2048 + r * 512 + (i0 + il)];
    }

    float sbv[4][4];
#pragma unroll
    for (int k = 0; k < 4; k++) {
        float sc = g_scale[b * 4 + k];
#pragma unroll
        for (int r = 0; r < 4; r++)
            sbv[k][r] = sc * g_mod[(size_t)b * FFDIM + k * 2048 + r * 512 + HDIM + t];
    }
    __syncthreads();

    float msum = 0.f;
#pragma unroll
    for (int q = 0; q < 16; q++) msum += g_magpart[b * 16 + q];
    const float inv = rsqrtf(msum * (1.0f / 65536.0f) + EPSC);
    const float be = g_beff;

#pragma unroll
    for (int il = 0; il < 16; il++) {
        const int pix = ((i0 + il) << 8) + t;
        float m[4];
#pragma unroll
        for (int k = 0; k < 4; k++) {
            float4 wk = wa4[il][k];
            float acc = be;
            acc = fmaf(wk.x, sbv[k][0], acc);
            acc = fmaf(wk.y, sbv[k][1], acc);
            acc = fmaf(wk.z, sbv[k][2], acc);
            acc = fmaf(wk.w, sbv[k][3], acc);
            m[k] = wm[(k << 16) + pix] * acc;
        }
        float2 A0 = *reinterpret_cast<const float2*>(&ws[2 * pix]);
        float2 A1 = *reinterpret_cast<const float2*>(&ws[131072 + 2 * pix]);
        float re = A1.x * m[0] - A1.y * m[1];
        float im = A1.x * m[1] - A1.y * m[0];
        float mwre = fmaf(re, inv, A0.x);
        float mwim = fmaf(im, inv, A0.y);
        float den = sqrtf(fmaf(m[2], m[2], fmaf(m[3], m[3], EPSC)));
        out[((size_t)b << 16) + pix] =
            __fdividef(fmaf(mwre, m[2], mwim * m[3]), den);
    }
}

// ---------------------------------------------------------------------------
// Launch
// ---------------------------------------------------------------------------
extern "C" void kernel_launch(void* const* d_in, const int* in_sizes, int n_in,
                              void* d_out, int out_size)
{
    const float* x      = (const float*)d_in[0];
    const float* Wt     = (const float*)d_in[1];
    const float* Wg     = (const float*)d_in[2];
    const float* ws     = (const float*)d_in[3];
    const float* wm     = (const float*)d_in[4];
    const float* conv_w = (const float*)d_in[5];
    const float* conv_b = (const float*)d_in[6];
    float* out = (float*)d_out;

    cudaFuncSetAttribute(k_gemm_mma,
                         cudaFuncAttributeMaxDynamicSharedMemorySize,
                         GEMM_SMEM_BYTES);

    k_gemm_mma<<<FFDIM / 64, 128, GEMM_SMEM_BYTES>>>(x, Wt, Wg);
    k_scale<<<BATCH * 4, 256>>>(conv_w, conv_b);
    k_mag<<<dim3(16, BATCH), 256>>>(ws, wm);
    k_final<<<dim3(16, BATCH), 256>>>(ws, wm, out);
}